// round 15
// baseline (speedup 1.0000x reference)
#include <cuda_runtime.h>
#include <cuda_fp16.h>
#include <cstdint>

// Problem constants
#define M_DIM 8192
#define N_DIM 4096
#define K_DIM 4096
#define ALPHA 0.01f
#define INPUT_SCALE 0.05f

// ---------------------------------------------------------------------------
// Scratch: fp16 + int8 copies of quantized A and W (no cudaMalloc allowed)
// ---------------------------------------------------------------------------
__device__ __half  g_xh[(size_t)M_DIM * K_DIM];   // 67 MB
__device__ __half  g_wh[(size_t)N_DIM * K_DIM];   // 33.5 MB
__device__ int8_t  g_xq[(size_t)M_DIM * K_DIM];   // 33.5 MB
__device__ int8_t  g_w8[(size_t)N_DIM * K_DIM];   // 16.8 MB

// ---------------------------------------------------------------------------
// Kernel 0: weight int32 -> fp16 + int8
// ---------------------------------------------------------------------------
__global__ void pack_w_kernel(const int* __restrict__ w32,
                              __half* __restrict__ wh, int8_t* __restrict__ w8) {
    int i = blockIdx.x * blockDim.x + threadIdx.x;
    const int n4 = (N_DIM * K_DIM) / 4;
    if (i >= n4) return;
    int4 v = reinterpret_cast<const int4*>(w32)[i];
    __half2 h0 = __halves2half2(__int2half_rn(v.x), __int2half_rn(v.y));
    __half2 h1 = __halves2half2(__int2half_rn(v.z), __int2half_rn(v.w));
    uint2 o;
    o.x = *reinterpret_cast<unsigned*>(&h0);
    o.y = *reinterpret_cast<unsigned*>(&h1);
    reinterpret_cast<uint2*>(wh)[i] = o;
    char4 c;
    c.x = (char)v.x; c.y = (char)v.y; c.z = (char)v.z; c.w = (char)v.w;
    reinterpret_cast<char4*>(w8)[i] = c;
}

// ---------------------------------------------------------------------------
// Kernel 1: quantize x fp32 -> int (round-half-even, clamp) -> fp16 + int8
// ---------------------------------------------------------------------------
__global__ void quant_kernel(const float* __restrict__ x,
                             __half* __restrict__ xh, int8_t* __restrict__ xq) {
    int i = blockIdx.x * blockDim.x + threadIdx.x;
    const int n4 = (M_DIM * K_DIM) / 4;
    if (i >= n4) return;
    float4 v = reinterpret_cast<const float4*>(x)[i];
    int q0 = __float2int_rn(__fdiv_rn(v.x, INPUT_SCALE));
    int q1 = __float2int_rn(__fdiv_rn(v.y, INPUT_SCALE));
    int q2 = __float2int_rn(__fdiv_rn(v.z, INPUT_SCALE));
    int q3 = __float2int_rn(__fdiv_rn(v.w, INPUT_SCALE));
    q0 = max(-128, min(127, q0));
    q1 = max(-128, min(127, q1));
    q2 = max(-128, min(127, q2));
    q3 = max(-128, min(127, q3));
    __half2 h0 = __halves2half2(__int2half_rn(q0), __int2half_rn(q1));
    __half2 h1 = __halves2half2(__int2half_rn(q2), __int2half_rn(q3));
    uint2 o;
    o.x = *reinterpret_cast<unsigned*>(&h0);
    o.y = *reinterpret_cast<unsigned*>(&h1);
    reinterpret_cast<uint2*>(xh)[i] = o;
    char4 c;
    c.x = (char)q0; c.y = (char)q1; c.z = (char)q2; c.w = (char)q3;
    reinterpret_cast<char4*>(xq)[i] = c;
}

// ---------------------------------------------------------------------------
// Kernel 2: hybrid GEMM — tensor pipe (HMMA, N[0:192)) + fma pipe (DP4A, N[192:256))
//   CTA 128x256, 512 threads: warps 0-11 HMMA (3/SMSP), warps 12-15 dp4a (1/SMSP)
// ---------------------------------------------------------------------------
#define BM 128
#define BN 256
#define BNH 192                      // HMMA-covered N per CTA
#define BKE 64                       // K elems per stage
#define ROWB 128                     // bytes per f16 smem row
#define KT (K_DIM / BKE)             // 64
#define THREADS 512

#define A16_BYTES (BM * ROWB)            // 16384
#define B16_BYTES (BNH * ROWB)           // 24576
#define AI8_BYTES (BM * 64)              // 8192
#define BI8_BYTES (64 * 80)              // 5120 (80B padded rows)
#define A16_OFF 0
#define B16_OFF (A16_OFF + A16_BYTES)
#define AI8_OFF (B16_OFF + B16_BYTES)
#define BI8_OFF (AI8_OFF + AI8_BYTES)
#define STAGE_BYTES (BI8_OFF + BI8_BYTES)          // 54272
#define SMEM_TOTAL (2 * STAGE_BYTES)               // 108544

__device__ __forceinline__ uint32_t smem_u32(const void* p) {
    uint32_t a;
    asm("{ .reg .u64 t; cvta.to.shared.u64 t, %1; cvt.u32.u64 %0, t; }" : "=r"(a) : "l"(p));
    return a;
}
__device__ __forceinline__ void cp16(uint32_t saddr, const void* gptr) {
    asm volatile("cp.async.cg.shared.global [%0], [%1], 16;\n" :: "r"(saddr), "l"(gptr));
}
__device__ __forceinline__ void ldsm4(unsigned* r, uint32_t saddr) {
    asm volatile("ldmatrix.sync.aligned.m8n8.x4.shared.b16 {%0,%1,%2,%3}, [%4];"
                 : "=r"(r[0]), "=r"(r[1]), "=r"(r[2]), "=r"(r[3]) : "r"(saddr));
}
__device__ __forceinline__ void lds128i(int* r, uint32_t saddr) {
    asm volatile("ld.shared.v4.b32 {%0,%1,%2,%3}, [%4];"
                 : "=r"(r[0]), "=r"(r[1]), "=r"(r[2]), "=r"(r[3]) : "r"(saddr));
}
__device__ __forceinline__ void mma_f16(float* c, const unsigned* a, const unsigned* b) {
    asm volatile(
        "mma.sync.aligned.m16n8k16.row.col.f32.f16.f16.f32 "
        "{%0,%1,%2,%3}, {%4,%5,%6,%7}, {%8,%9}, {%0,%1,%2,%3};\n"
        : "+f"(c[0]), "+f"(c[1]), "+f"(c[2]), "+f"(c[3])
        : "r"(a[0]), "r"(a[1]), "r"(a[2]), "r"(a[3]),
          "r"(b[0]), "r"(b[1]));
}

__global__ __launch_bounds__(THREADS, 1)
void gemm_hybrid_kernel(const __half* __restrict__ Ah,
                        const __half* __restrict__ Wh,
                        const int8_t* __restrict__ Aq,
                        const int8_t* __restrict__ W8,
                        const float* __restrict__ bias,
                        float* __restrict__ out) {
    extern __shared__ __align__(1024) int8_t smem[];
    const uint32_t sbase = smem_u32(smem);

    const int tid  = threadIdx.x;
    const int bm   = blockIdx.y * BM;
    const int bn   = blockIdx.x * BN;
    const int wid  = tid >> 5;
    const int lane = tid & 31;

    const int8_t* gA = reinterpret_cast<const int8_t*>(Ah);
    const int8_t* gB = reinterpret_cast<const int8_t*>(Wh);
    const size_t rowbytes = (size_t)K_DIM * 2;

    // ---- stage loader (all 512 threads) ----
    auto load_stage = [&](int s, int kt) {
        const uint32_t st = sbase + s * STAGE_BYTES;
        // A f16: 1024 chunks, 2/thread
        {
            const int8_t* ga = gA + (size_t)bm * rowbytes + (size_t)kt * 128;
#pragma unroll
            for (int j = 0; j < 2; j++) {
                int c = j * THREADS + tid;
                int row = c >> 3, col = (c & 7) * 16;
                uint32_t soff = (uint32_t)(row * ROWB + (col ^ ((row & 7) * 16)));
                cp16(st + A16_OFF + soff, ga + (size_t)row * rowbytes + col);
            }
        }
        // B f16: 1536 chunks (192 rows), 3/thread
        {
            const int8_t* gb = gB + (size_t)bn * rowbytes + (size_t)kt * 128;
#pragma unroll
            for (int j = 0; j < 3; j++) {
                int c = j * THREADS + tid;
                int row = c >> 3, col = (c & 7) * 16;
                uint32_t soff = (uint32_t)(row * ROWB + (col ^ ((row & 7) * 16)));
                cp16(st + B16_OFF + soff, gb + (size_t)row * rowbytes + col);
            }
        }
        // A i8: 512 chunks, 1/thread (linear 64B rows, broadcast-read later)
        {
            int row = tid >> 2, col = (tid & 3) * 16;
            cp16(st + AI8_OFF + (uint32_t)(row * 64 + col),
                 Aq + (size_t)(bm + row) * K_DIM + (size_t)kt * 64 + col);
        }
        // B i8: 256 chunks, threads < 256 (80B padded rows)
        if (tid < 256) {
            int row = tid >> 2, col = (tid & 3) * 16;
            cp16(st + BI8_OFF + (uint32_t)(row * 80 + col),
                 W8 + (size_t)(bn + BNH + row) * K_DIM + (size_t)kt * 64 + col);
        }
        asm volatile("cp.async.commit_group;\n");
    };

    load_stage(0, 0);
    load_stage(1, 1);

    if (wid < 12) {
        // =================== HMMA warps: N in [0, 192) ===================
        const int wm = (wid / 6) * 64;        // 2 along M
        const int wn = (wid % 6) * 32;        // 6 along N
        const int l15 = lane & 15;
        const int chi = (lane & 16) ? 16 : 0;

        float acc[4][4][4];
#pragma unroll
        for (int i = 0; i < 4; i++)
#pragma unroll
            for (int j = 0; j < 4; j++)
#pragma unroll
                for (int r = 0; r < 4; r++) acc[i][j][r] = 0.0f;

        for (int kt = 0; kt < KT; kt++) {
            const int cur = kt & 1;
            asm volatile("cp.async.wait_group 1;\n");
            __syncthreads();
            const uint32_t sa = sbase + cur * STAGE_BYTES + A16_OFF;
            const uint32_t sb = sbase + cur * STAGE_BYTES + B16_OFF;
#pragma unroll
            for (int ks = 0; ks < 4; ks++) {
                const int colk = ks * 32 + chi;
                unsigned a[4][4];
                unsigned bfr[4][2];
#pragma unroll
                for (int j = 0; j < 2; j++) {
                    unsigned t[4];
                    int row = wn + j * 16 + l15;
                    ldsm4(t, sb + row * ROWB + (colk ^ ((row & 7) * 16)));
                    bfr[2 * j][0]     = t[0]; bfr[2 * j][1]     = t[2];
                    bfr[2 * j + 1][0] = t[1]; bfr[2 * j + 1][1] = t[3];
                }
#pragma unroll
                for (int mt = 0; mt < 4; mt++) {
                    int row = wm + mt * 16 + l15;
                    ldsm4(a[mt], sa + row * ROWB + (colk ^ ((row & 7) * 16)));
                }
#pragma unroll
                for (int mt = 0; mt < 4; mt++)
#pragma unroll
                    for (int nt = 0; nt < 4; nt++)
                        mma_f16(acc[mt][nt], a[mt], bfr[nt]);
            }
            __syncthreads();
            if (kt + 2 < KT) load_stage(cur, kt + 2);
        }

        const int g = lane >> 2, tg = lane & 3;
#pragma unroll
        for (int mt = 0; mt < 4; mt++) {
            const int m0 = bm + wm + mt * 16 + g;
#pragma unroll
            for (int nt = 0; nt < 4; nt++) {
                const int n0 = bn + wn + nt * 8 + tg * 2;
                const float b0 = bias[n0];
                const float b1 = bias[n0 + 1];
                float2 v0, v1;
                v0.x = ALPHA * acc[mt][nt][0] + b0;
                v0.y = ALPHA * acc[mt][nt][1] + b1;
                v1.x = ALPHA * acc[mt][nt][2] + b0;
                v1.y = ALPHA * acc[mt][nt][3] + b1;
                *reinterpret_cast<float2*>(&out[(size_t)m0 * N_DIM + n0])       = v0;
                *reinterpret_cast<float2*>(&out[(size_t)(m0 + 8) * N_DIM + n0]) = v1;
            }
        }
    } else {
        // =================== dp4a warps: N in [192, 256) ===================
        // warp (wid-12) owns M rows [dw*32, dw*32+32); lane owns cols n0=lane, n1=lane+32
        const int dw = wid - 12;
        const int mrow0 = dw * 32;

        int acc0[32], acc1[32];
#pragma unroll
        for (int m = 0; m < 32; m++) { acc0[m] = 0; acc1[m] = 0; }

        for (int kt = 0; kt < KT; kt++) {
            const int cur = kt & 1;
            asm volatile("cp.async.wait_group 1;\n");
            __syncthreads();
            const uint32_t ai8 = sbase + cur * STAGE_BYTES + AI8_OFF;
            const uint32_t bi8 = sbase + cur * STAGE_BYTES + BI8_OFF;

            int bw0[16], bw1[16];
#pragma unroll
            for (int q = 0; q < 4; q++) {
                lds128i(&bw0[q * 4], bi8 + lane * 80 + q * 16);
                lds128i(&bw1[q * 4], bi8 + (lane + 32) * 80 + q * 16);
            }
#pragma unroll
            for (int q = 0; q < 4; q++) {
#pragma unroll
                for (int m = 0; m < 32; m++) {
                    int aw[4];
                    lds128i(aw, ai8 + (mrow0 + m) * 64 + q * 16);  // broadcast
#pragma unroll
                    for (int j = 0; j < 4; j++) {
                        acc0[m] = __dp4a(aw[j], bw0[q * 4 + j], acc0[m]);
                        acc1[m] = __dp4a(aw[j], bw1[q * 4 + j], acc1[m]);
                    }
                }
            }
            __syncthreads();
            if (kt + 2 < KT) load_stage(cur, kt + 2);
        }

        const float b0 = bias[bn + BNH + lane];
        const float b1 = bias[bn + BNH + 32 + lane];
#pragma unroll
        for (int m = 0; m < 32; m++) {
            const size_t row = (size_t)(bm + mrow0 + m) * N_DIM + bn + BNH;
            out[row + lane]      = ALPHA * (float)acc0[m] + b0;
            out[row + 32 + lane] = ALPHA * (float)acc1[m] + b1;
        }
    }
}

// ---------------------------------------------------------------------------
// Launch
// ---------------------------------------------------------------------------
extern "C" void kernel_launch(void* const* d_in, const int* in_sizes, int n_in,
                              void* d_out, int out_size) {
    const float* x    = (const float*)d_in[0];
    const int*   w32  = (const int*)d_in[1];   // weight delivered as int32
    const float* bias = (const float*)d_in[2];
    float*       out  = (float*)d_out;

    __half *xh, *wh;
    int8_t *xq, *w8;
    cudaGetSymbolAddress((void**)&xh, g_xh);
    cudaGetSymbolAddress((void**)&wh, g_wh);
    cudaGetSymbolAddress((void**)&xq, g_xq);
    cudaGetSymbolAddress((void**)&w8, g_w8);

    cudaFuncSetAttribute(gemm_hybrid_kernel,
                         cudaFuncAttributeMaxDynamicSharedMemorySize, SMEM_TOTAL);

    {   // 0) weights int32 -> fp16 + int8
        const int n4 = (N_DIM * K_DIM) / 4;
        pack_w_kernel<<<(n4 + 255) / 256, 256>>>(w32, wh, w8);
    }
    {   // 1) quantize activations fp32 -> fp16 + int8
        const int n4 = (M_DIM * K_DIM) / 4;
        quant_kernel<<<(n4 + 255) / 256, 256>>>(x, xh, xq);
    }
    {   // 2) hybrid tensor+fma GEMM + dequant epilogue
        dim3 grid(N_DIM / BN, M_DIM / BM);  // (16, 64)
        gemm_hybrid_kernel<<<grid, THREADS, SMEM_TOTAL>>>(xh, wh, xq, w8, bias, out);
    }
}

// round 16
// speedup vs baseline: 1.4822x; 1.4822x over previous
#include <cuda_runtime.h>
#include <cuda_fp16.h>
#include <cstdint>

// Problem constants
#define M_DIM 8192
#define N_DIM 4096
#define K_DIM 4096
#define ALPHA 0.01f
#define INPUT_SCALE 0.05f

// ---------------------------------------------------------------------------
// Scratch (no cudaMalloc allowed): fp16 copies of quantized A and W
// ---------------------------------------------------------------------------
__device__ __half g_xh[(size_t)M_DIM * K_DIM];   // 67 MB
__device__ __half g_wh[(size_t)N_DIM * K_DIM];   // 33.5 MB

// ---------------------------------------------------------------------------
// Kernel 0: fused prep — x fp32 -> quantized fp16, weight int32 -> fp16
// Range split over one linear float4/int4 index space.
// ---------------------------------------------------------------------------
#define N4X ((M_DIM * K_DIM) / 4)     // 8388608
#define N4W ((N_DIM * K_DIM) / 4)     // 4194304

__global__ void prep_kernel(const float* __restrict__ x, const int* __restrict__ w32,
                            __half* __restrict__ xh, __half* __restrict__ wh) {
    int i = blockIdx.x * blockDim.x + threadIdx.x;
    if (i < N4X) {
        float4 v = reinterpret_cast<const float4*>(x)[i];
        int q0 = __float2int_rn(__fdiv_rn(v.x, INPUT_SCALE));
        int q1 = __float2int_rn(__fdiv_rn(v.y, INPUT_SCALE));
        int q2 = __float2int_rn(__fdiv_rn(v.z, INPUT_SCALE));
        int q3 = __float2int_rn(__fdiv_rn(v.w, INPUT_SCALE));
        q0 = max(-128, min(127, q0));
        q1 = max(-128, min(127, q1));
        q2 = max(-128, min(127, q2));
        q3 = max(-128, min(127, q3));
        __half2 h0 = __halves2half2(__int2half_rn(q0), __int2half_rn(q1));
        __half2 h1 = __halves2half2(__int2half_rn(q2), __int2half_rn(q3));
        uint2 o;
        o.x = *reinterpret_cast<unsigned*>(&h0);
        o.y = *reinterpret_cast<unsigned*>(&h1);
        reinterpret_cast<uint2*>(xh)[i] = o;
    } else {
        int j = i - N4X;
        if (j >= N4W) return;
        int4 v = reinterpret_cast<const int4*>(w32)[j];
        __half2 h0 = __halves2half2(__int2half_rn(v.x), __int2half_rn(v.y));
        __half2 h1 = __halves2half2(__int2half_rn(v.z), __int2half_rn(v.w));
        uint2 o;
        o.x = *reinterpret_cast<unsigned*>(&h0);
        o.y = *reinterpret_cast<unsigned*>(&h1);
        reinterpret_cast<uint2*>(wh)[j] = o;
    }
}

// ---------------------------------------------------------------------------
// Kernel 1: fp16 GEMM via HMMA m16n8k16 (f32 accum)
//   CTA 128x128, 8 warps in 2(M) x 4(N), warp tile 64x32
//   3-stage cp.async ring, swizzled smem, ldmatrix, ONE barrier per k-tile
// ---------------------------------------------------------------------------
#define BM 128
#define BN 128
#define BKE 64                        // K elems per stage (fp16 => 128 B rows)
#define ROWB 128                      // bytes per smem row
#define STAGES 3
#define KT (K_DIM / BKE)              // 64
#define THREADS 256

#define TILE_BYTES (BM * ROWB)        // 16 KB
#define SMEM_STAGE_BYTES (2 * TILE_BYTES)
#define SMEM_TOTAL (STAGES * SMEM_STAGE_BYTES)   // 96 KB -> 2 CTAs/SM

__device__ __forceinline__ uint32_t smem_u32(const void* p) {
    uint32_t a;
    asm("{ .reg .u64 t; cvta.to.shared.u64 t, %1; cvt.u32.u64 %0, t; }" : "=r"(a) : "l"(p));
    return a;
}
__device__ __forceinline__ void cp16(uint32_t saddr, const void* gptr) {
    asm volatile("cp.async.cg.shared.global [%0], [%1], 16;\n" :: "r"(saddr), "l"(gptr));
}
__device__ __forceinline__ void ldsm4(unsigned* r, uint32_t saddr) {
    asm volatile("ldmatrix.sync.aligned.m8n8.x4.shared.b16 {%0,%1,%2,%3}, [%4];"
                 : "=r"(r[0]), "=r"(r[1]), "=r"(r[2]), "=r"(r[3]) : "r"(saddr));
}
__device__ __forceinline__ void mma_f16(float* c, const unsigned* a, const unsigned* b) {
    asm volatile(
        "mma.sync.aligned.m16n8k16.row.col.f32.f16.f16.f32 "
        "{%0,%1,%2,%3}, {%4,%5,%6,%7}, {%8,%9}, {%0,%1,%2,%3};\n"
        : "+f"(c[0]), "+f"(c[1]), "+f"(c[2]), "+f"(c[3])
        : "r"(a[0]), "r"(a[1]), "r"(a[2]), "r"(a[3]),
          "r"(b[0]), "r"(b[1]));
}

__global__ __launch_bounds__(THREADS, 2)
void gemm_f16_kernel(const __half* __restrict__ Ah,
                     const __half* __restrict__ Wh,
                     const float* __restrict__ bias,
                     float* __restrict__ out) {
    extern __shared__ __align__(1024) int8_t smem[];
    const uint32_t sbase = smem_u32(smem);

    const int tid  = threadIdx.x;
    const int bm   = blockIdx.y * BM;
    const int bn   = blockIdx.x * BN;
    const int w    = tid >> 5;
    const int lane = tid & 31;
    const int wm   = (w >> 2) * 64;   // 2 warps along M
    const int wn   = (w & 3) * 32;    // 4 warps along N
    const int g    = lane >> 2;
    const int tg   = lane & 3;

    float acc[4][4][4];
#pragma unroll
    for (int i = 0; i < 4; i++)
#pragma unroll
        for (int j = 0; j < 4; j++)
#pragma unroll
            for (int r = 0; r < 4; r++) acc[i][j][r] = 0.0f;

    const int8_t* gA = reinterpret_cast<const int8_t*>(Ah);
    const int8_t* gB = reinterpret_cast<const int8_t*>(Wh);
    const size_t rowbytes = (size_t)K_DIM * 2;

    auto stA = [&](int s) { return sbase + s * SMEM_STAGE_BYTES; };
    auto stB = [&](int s) { return sbase + s * SMEM_STAGE_BYTES + TILE_BYTES; };

    auto load_stage = [&](int s, int kt) {
        const int8_t* ga = gA + (size_t)bm * rowbytes + (size_t)kt * ROWB;
        const int8_t* gb = gB + (size_t)bn * rowbytes + (size_t)kt * ROWB;
        const uint32_t sa = stA(s), sb = stB(s);
#pragma unroll
        for (int j = 0; j < 4; j++) {
            int c   = j * THREADS + tid;
            int row = c >> 3;
            int col = (c & 7) * 16;
            uint32_t soff = (uint32_t)(row * ROWB + (col ^ ((row & 7) * 16)));
            cp16(sa + soff, ga + (size_t)row * rowbytes + col);
            cp16(sb + soff, gb + (size_t)row * rowbytes + col);
        }
        asm volatile("cp.async.commit_group;\n");
    };

    const int l15 = lane & 15;
    const int chi = (lane & 16) ? 16 : 0;

    load_stage(0, 0);
    load_stage(1, 1);

    for (int kt = 0; kt < KT; kt++) {
        const int cur = kt % STAGES;
        asm volatile("cp.async.wait_group 1;\n");
        __syncthreads();
        // Refill stage (kt+2)%3: consumed at kt-1; all threads passed the barrier.
        if (kt + 2 < KT) load_stage((kt + 2) % STAGES, kt + 2);

        const uint32_t sa = stA(cur), sb = stB(cur);
#pragma unroll
        for (int ks = 0; ks < 4; ks++) {          // 4 x (K=16 fp16 = 32 B)
            const int colk = ks * 32 + chi;
            unsigned a[4][4];
            unsigned bfr[4][2];
#pragma unroll
            for (int j = 0; j < 2; j++) {
                unsigned t[4];
                int row = wn + j * 16 + l15;
                ldsm4(t, sb + row * ROWB + (colk ^ ((row & 7) * 16)));
                bfr[2 * j][0]     = t[0]; bfr[2 * j][1]     = t[2];
                bfr[2 * j + 1][0] = t[1]; bfr[2 * j + 1][1] = t[3];
            }
#pragma unroll
            for (int mt = 0; mt < 4; mt++) {
                int row = wm + mt * 16 + l15;
                ldsm4(a[mt], sa + row * ROWB + (colk ^ ((row & 7) * 16)));
            }
#pragma unroll
            for (int mt = 0; mt < 4; mt++)
#pragma unroll
                for (int nt = 0; nt < 4; nt++)
                    mma_f16(acc[mt][nt], a[mt], bfr[nt]);
        }
    }

    // Epilogue: y = ALPHA * acc + bias[n]
#pragma unroll
    for (int mt = 0; mt < 4; mt++) {
        const int m0 = bm + wm + mt * 16 + g;
#pragma unroll
        for (int nt = 0; nt < 4; nt++) {
            const int n0 = bn + wn + nt * 8 + tg * 2;
            const float b0 = bias[n0];
            const float b1 = bias[n0 + 1];
            float2 v0, v1;
            v0.x = ALPHA * acc[mt][nt][0] + b0;
            v0.y = ALPHA * acc[mt][nt][1] + b1;
            v1.x = ALPHA * acc[mt][nt][2] + b0;
            v1.y = ALPHA * acc[mt][nt][3] + b1;
            *reinterpret_cast<float2*>(&out[(size_t)m0 * N_DIM + n0])       = v0;
            *reinterpret_cast<float2*>(&out[(size_t)(m0 + 8) * N_DIM + n0]) = v1;
        }
    }
}

// ---------------------------------------------------------------------------
// Launch
// ---------------------------------------------------------------------------
extern "C" void kernel_launch(void* const* d_in, const int* in_sizes, int n_in,
                              void* d_out, int out_size) {
    const float* x    = (const float*)d_in[0];
    const int*   w32  = (const int*)d_in[1];   // weight delivered as int32
    const float* bias = (const float*)d_in[2];
    float*       out  = (float*)d_out;

    __half *xh, *wh;
    cudaGetSymbolAddress((void**)&xh, g_xh);
    cudaGetSymbolAddress((void**)&wh, g_wh);

    cudaFuncSetAttribute(gemm_f16_kernel, cudaFuncAttributeMaxDynamicSharedMemorySize,
                         SMEM_TOTAL);

    {   // 0) fused prep: quantize x -> fp16, pack W -> fp16
        const int total = N4X + N4W;
        prep_kernel<<<(total + 255) / 256, 256>>>(x, w32, xh, wh);
    }
    {   // 1) fp16 HMMA GEMM + dequant epilogue
        dim3 grid(N_DIM / BN, M_DIM / BM);  // (32, 64)
        gemm_f16_kernel<<<grid, THREADS, SMEM_TOTAL>>>(xh, wh, bias, out);
    }
}